// round 10
// baseline (speedup 1.0000x reference)
#include <cuda_runtime.h>
#include <cuda_bf16.h>
#include <cstdint>

// Problem constants
#define B_   64
#define S_   512
#define H_   768
#define P2_  46
#define MT   64            // M rows per CTA
#define CK   32            // K elems per chunk
#define NIT  12            // chunks per k-half (24 total, split across warp halves)

// B smem: per buffer {W_hi 48x80B, W_lo 48x80B}; 3 buffers per k-half (6 total).
// Ring depth 3 is REQUIRED: prefetch distance is 2, so the written buffer
// (it+2)%3 must differ from the one being read (it%3) -- depth 2 races.
#define WB    3840         // 48*80: lo-half offset within buffer
#define WBUF  7680
#define NT6   640          // 8 rows * 80B per n-tile

// Scratch (no cudaMalloc allowed)
__device__ float g_sdot[B_ * 48];
__device__ int   g_cue[B_];
// K-PERMUTED split W: within each 16-col group, orig col o stored at position
// pos = 2*(o>>2) + (o&1) + 8*((o>>1)&1). A-side fragments use the same map
// implicitly (float4 loads land in frag regs at exactly these positions), so
// the GEMM sum over K is unchanged. Rows 46-47 zeroed.
__device__ __nv_bfloat16 g_wsplit[2][48 * H_];

// ---------------------------------------------------------------------------
// Combo kernel: blocks [0,144) = permuted W split; blocks [144,208) = prep.
// ---------------------------------------------------------------------------
__global__ void __launch_bounds__(256) combo_kernel(
    const float* __restrict__ hs, const int* __restrict__ ids,
    const int* __restrict__ mask, const float* __restrict__ W)
{
    __shared__ float s[H_];
    __shared__ int cue_sh;
    const int tid = threadIdx.x;

    if (blockIdx.x < 144) {
        const int idx = blockIdx.x * 256 + tid;      // < 48*768 exactly
        const int row = idx / H_;
        const int K   = idx - row * H_;
        const float x = (row < P2_) ? W[idx] : 0.0f;
        __nv_bfloat16 hi = __float2bfloat16(x);
        __nv_bfloat16 lo = __float2bfloat16(x - __bfloat162float(hi));
        const int o   = K & 15;
        const int pos = ((o >> 2) * 2) + (o & 1) + ((o >> 1) & 1) * 8;
        const int didx = row * H_ + (K & ~15) + pos;
        g_wsplit[0][didx] = hi;
        g_wsplit[1][didx] = lo;
        return;
    }

    const int b = blockIdx.x - 144;
    if (tid == 0) cue_sh = 0;
    __syncthreads();

    const int id0 = ids[b * 2 + 0], id1 = ids[b * 2 + 1];
    const float* h0 = hs + ((size_t)b * S_ + id0) * H_;
    const float* h1 = hs + ((size_t)b * S_ + id1) * H_;
    #pragma unroll
    for (int h = tid; h < H_; h += 256) s[h] = h0[h] + h1[h];

    int local = 0;
    #pragma unroll
    for (int t = tid; t < S_; t += 256) local += mask[b * S_ + t];
    #pragma unroll
    for (int o = 16; o; o >>= 1) local += __shfl_down_sync(0xffffffffu, local, o);
    if ((tid & 31) == 0) atomicAdd(&cue_sh, local);
    __syncthreads();

    const int warp = tid >> 5, lane = tid & 31;
    for (int p = warp; p < P2_; p += 8) {
        const float* wp = W + (size_t)p * H_;
        float acc = 0.f;
        #pragma unroll
        for (int h = 0; h < H_; h += 32) acc += s[h + lane] * __ldg(wp + h + lane);
        #pragma unroll
        for (int o = 16; o; o >>= 1) acc += __shfl_down_sync(0xffffffffu, acc, o);
        if (lane == 0) g_sdot[b * 48 + p] = acc;
    }
    if (tid == 0) g_cue[b] = cue_sh;
}

// ---------------------------------------------------------------------------
// Warp-MMA helpers (base ISA, compiles on plain sm_103 target)
// ---------------------------------------------------------------------------
__device__ __forceinline__ void ldsm4(uint32_t* r, uint32_t addr) {
    asm volatile("ldmatrix.sync.aligned.m8n8.x4.shared.b16 {%0,%1,%2,%3}, [%4];"
                 : "=r"(r[0]), "=r"(r[1]), "=r"(r[2]), "=r"(r[3]) : "r"(addr));
}
__device__ __forceinline__ void mma_bf16(float* c, const uint32_t* a,
                                         const uint32_t* b) {
    asm volatile(
        "mma.sync.aligned.m16n8k16.row.col.f32.bf16.bf16.f32 "
        "{%0,%1,%2,%3}, {%4,%5,%6,%7}, {%8,%9}, {%0,%1,%2,%3};"
        : "+f"(c[0]), "+f"(c[1]), "+f"(c[2]), "+f"(c[3])
        : "r"(a[0]), "r"(a[1]), "r"(a[2]), "r"(a[3]), "r"(b[0]), "r"(b[1]));
}
__device__ __forceinline__ uint32_t cvt2(float hiE, float loE) {
    uint32_t d;
    asm("cvt.rn.bf16x2.f32 %0, %1, %2;" : "=r"(d) : "f"(hiE), "f"(loE));
    return d;
}
__device__ __forceinline__ void cpa16(uint32_t dst, const void* src) {
    asm volatile("cp.async.ca.shared.global [%0], [%1], 16;"
                 :: "r"(dst), "l"(src));
}

// ---------------------------------------------------------------------------
// Main: K-split split-precision bf16 mma.sync GEMM + fused epilogue.
// 512 CTAs x 256 threads. Warp w: k-half h=w>>2 (chunks h*12..h*12+11),
// row group wr=w&3 (rows wr*16..+15). A: LDG.128 direct-to-fragment via the
// K permutation (no smem, no shuffles). B: cp.async ring, 3 buffers per half.
// After the loop, half-1 warps dump partial accs to smem; half-0 adds and
// runs the epilogue. D = Ah*Wh + Ah*Wl + Al*Wh.
// ---------------------------------------------------------------------------
__global__ void __launch_bounds__(256, 3) main_kernel(
    const float* __restrict__ hs, const float* __restrict__ bias,
    float* __restrict__ out)
{
    __shared__ __align__(16) char smem[6 * WBUF];    // 46080 B
    const uint32_t sb = (uint32_t)__cvta_generic_to_shared(smem);
    const int tid = threadIdx.x, w = tid >> 5, l = tid & 31;
    const int h  = w >> 2;              // k-half
    const int wr = w & 3;               // row group within CTA
    const int r0 = blockIdx.x * MT, b = r0 >> 9;

    // --- B producer: both halves' chunk `it`; 768 x 16B segs, 3/thread ---
    auto cpBoth = [&](int it) {
        const int sl = it % 3;           // ring slot
        #pragma unroll
        for (int i = 0; i < 3; i++) {
            int g  = tid + i * 256;          // 0..767
            int hh = g / 384;                // which k-half's buffer
            int r  = g - hh * 384;
            int p  = r / 192;                // hi/lo
            int rr = (r % 192) >> 2;         // row 0..47
            int q  = r & 3;                  // 16B granule
            cpa16(sb + (hh * 3 + sl) * WBUF + p * WB + rr * 80 + q * 16,
                  &g_wsplit[p][rr * H_ + (hh * NIT + it) * CK + q * 8]);
        }
        asm volatile("cp.async.commit_group;");
    };

    // --- A: direct-to-fragment LDG.128 (permuted K) ---
    const int ar  = wr * 16 + (l >> 2);
    const int ac4 = (l & 3) * 4;
    const float* gA = hs + (size_t)(r0 + ar) * H_ + ac4;
    float4 aF[4];                        // [g*2 + rowSel]
    auto ldA = [&](int ckG) {
        const int kb = ckG * CK;
        aF[0] = *(const float4*)(gA + kb);
        aF[1] = *(const float4*)(gA + 8 * H_ + kb);
        aF[2] = *(const float4*)(gA + kb + 16);
        aF[3] = *(const float4*)(gA + 8 * H_ + kb + 16);
    };

    float acc[6][4];
    #pragma unroll
    for (int nt = 0; nt < 6; nt++)
        #pragma unroll
        for (int k = 0; k < 4; k++) acc[nt][k] = 0.f;

    cpBoth(0); cpBoth(1);
    ldA(h * NIT);

    // ldmatrix x4 B address: lanes 0-15 -> n-tile nt, lanes 16-31 -> nt+1
    const int il = l & 15;
    const uint32_t bA = (uint32_t)((il & 7) * 80 + (il >> 3) * 16 + (l >> 4) * NT6);

    for (int it = 0; it < NIT; it++) {
        if (it + 1 < NIT)
            asm volatile("cp.async.wait_group 1;" ::: "memory");
        else
            asm volatile("cp.async.wait_group 0;" ::: "memory");
        __syncthreads();                 // B(it) visible; slot (it+2)%3 free
        if (it + 2 < NIT) cpBoth(it + 2);

        // Convert current A float4s to hi/lo fragments (positions built-in):
        // a0=(r, pos 2c,2c+1)<-orig 4c,4c+1 ; a2=(r, pos 2c+8,2c+9)<-4c+2,4c+3
        uint32_t ahi[8], alo[8];
        #pragma unroll
        for (int g2 = 0; g2 < 2; g2++)
            #pragma unroll
            for (int rj = 0; rj < 2; rj++) {
                float4 v = aF[g2 * 2 + rj];
                uint32_t hxy = cvt2(v.y, v.x);
                uint32_t hzw = cvt2(v.w, v.z);
                float e0 = __uint_as_float(hxy << 16);
                float e1 = __uint_as_float(hxy & 0xffff0000u);
                float e2 = __uint_as_float(hzw << 16);
                float e3 = __uint_as_float(hzw & 0xffff0000u);
                ahi[g2 * 4 + rj]     = hxy;
                ahi[g2 * 4 + 2 + rj] = hzw;
                alo[g2 * 4 + rj]     = cvt2(v.y - e1, v.x - e0);
                alo[g2 * 4 + 2 + rj] = cvt2(v.w - e3, v.z - e2);
            }
        if (it + 1 < NIT) ldA(h * NIT + it + 1);

        const uint32_t sbase = sb + (h * 3 + it % 3) * WBUF;
        #pragma unroll
        for (int ks = 0; ks < 2; ks++) {
            const uint32_t* ah = ahi + ks * 4;
            const uint32_t* al = alo + ks * 4;
            #pragma unroll
            for (int pp = 0; pp < 3; pp++) {   // n-tile pairs (0,1)(2,3)(4,5)
                uint32_t bh[4], bl[4];
                const uint32_t ba = sbase + pp * 2 * NT6 + bA + ks * 32;
                ldsm4(bh, ba);
                ldsm4(bl, ba + WB);
                mma_bf16(acc[2 * pp],     ah, bh);
                mma_bf16(acc[2 * pp],     ah, bl);
                mma_bf16(acc[2 * pp],     al, bh);
                mma_bf16(acc[2 * pp + 1], ah, bh + 2);
                mma_bf16(acc[2 * pp + 1], ah, bl + 2);
                mma_bf16(acc[2 * pp + 1], al, bh + 2);
            }
        }
    }

    // --- K-split reduction: half-1 dumps partials into smem (B ring dead) ---
    __syncthreads();
    float* rbuf = (float*)smem;              // [64][48] f32 = 12 KB
    const int mrow = wr * 16 + (l >> 2);
    if (h == 1) {
        #pragma unroll
        for (int nt = 0; nt < 6; nt++) {
            const int col = nt * 8 + (l & 3) * 2;
            *(float2*)&rbuf[mrow * 48 + col]       = make_float2(acc[nt][0], acc[nt][1]);
            *(float2*)&rbuf[(mrow + 8) * 48 + col] = make_float2(acc[nt][2], acc[nt][3]);
        }
    }
    __syncthreads();
    if (h == 1) return;

    // --- Epilogue (half-0): x = D + bias + (t<cue)*sdot ; out = sigmoid^4 ---
    const int cue = g_cue[b];
    const int t0  = (r0 & (S_ - 1)) + mrow;
    const float f0 = (t0 < cue) ? 1.0f : 0.0f;
    const float f1 = (t0 + 8 < cue) ? 1.0f : 0.0f;
    float* o0 = out + (size_t)(r0 + mrow) * P2_;
    float* o1 = o0 + 8 * P2_;

    #pragma unroll
    for (int nt = 0; nt < 6; nt++) {
        const int col = nt * 8 + (l & 3) * 2;
        if (col >= P2_) continue;                // drops cols 46,47
        float2 p0 = *(const float2*)&rbuf[mrow * 48 + col];
        float2 p1 = *(const float2*)&rbuf[(mrow + 8) * 48 + col];
        const float b0 = __ldg(bias + col),     b1 = __ldg(bias + col + 1);
        const float s0 = g_sdot[b * 48 + col],  s1 = g_sdot[b * 48 + col + 1];

        float x00 = acc[nt][0] + p0.x + b0 + f0 * s0;
        float x01 = acc[nt][1] + p0.y + b1 + f0 * s1;
        float x10 = acc[nt][2] + p1.x + b0 + f1 * s0;
        float x11 = acc[nt][3] + p1.y + b1 + f1 * s1;
        float g00 = 1.f / (1.f + __expf(-x00)); g00 *= g00; g00 *= g00;
        float g01 = 1.f / (1.f + __expf(-x01)); g01 *= g01; g01 *= g01;
        float g10 = 1.f / (1.f + __expf(-x10)); g10 *= g10; g10 *= g10;
        float g11 = 1.f / (1.f + __expf(-x11)); g11 *= g11; g11 *= g11;
        *(float2*)(o0 + col) = make_float2(g00, g01);
        *(float2*)(o1 + col) = make_float2(g10, g11);
    }
}

// ---------------------------------------------------------------------------
// Launch
// ---------------------------------------------------------------------------
extern "C" void kernel_launch(void* const* d_in, const int* in_sizes, int n_in,
                              void* d_out, int out_size)
{
    const float* hs   = (const float*)d_in[0];  // [64,512,768] f32
    const int*   ids  = (const int*)  d_in[1];  // [64,2] i32
    const int*   mask = (const int*)  d_in[2];  // [64,512] i32
    const float* W    = (const float*)d_in[3];  // [46,768] f32
    const float* bias = (const float*)d_in[4];  // [46] f32
    float*       out  = (float*)d_out;          // [64,512,46] f32

    combo_kernel<<<144 + B_, 256>>>(hs, ids, mask, W);
    main_kernel<<<(B_ * S_) / MT, 256>>>(hs, bias, out);
}

// round 14
// speedup vs baseline: 1.0913x; 1.0913x over previous
#include <cuda_runtime.h>
#include <cuda_bf16.h>
#include <cstdint>

// Problem constants
#define B_   64
#define S_   512
#define H_   768
#define P2_  46
#define MT   64            // M rows per CTA
#define CK   32            // K elems per chunk
#define NIT  12            // chunks per k-half (24 total, split across warp halves)

// B smem: per buffer {W_hi 48x80B, W_lo 48x80B}; 3 buffers per k-half (6 total).
// Ring depth 3 is REQUIRED at prefetch distance 2 (depth 2 races: R9 failure).
#define WB    3840         // 48*80: lo-half offset within buffer
#define WBUF  7680
#define NT6   640          // 8 rows * 80B per n-tile

// Scratch (no cudaMalloc allowed)
__device__ float g_sdot[B_ * 48];
__device__ int   g_cue[B_];
// K-PERMUTED split W: within each 16-col group, orig col o stored at position
// pos = 2*(o>>2) + (o&1) + 8*((o>>1)&1). A-side float4 fragment loads realize
// the same map, so the GEMM sum over K is unchanged. Rows 46-47 zeroed.
__device__ __nv_bfloat16 g_wsplit[2][48 * H_];

// ---------------------------------------------------------------------------
// Combo kernel: blocks [0,144) = permuted W split; blocks [144,208) = prep.
// ---------------------------------------------------------------------------
__global__ void __launch_bounds__(256) combo_kernel(
    const float* __restrict__ hs, const int* __restrict__ ids,
    const int* __restrict__ mask, const float* __restrict__ W)
{
    __shared__ float s[H_];
    __shared__ int cue_sh;
    const int tid = threadIdx.x;

    if (blockIdx.x < 144) {
        const int idx = blockIdx.x * 256 + tid;      // < 48*768 exactly
        const int row = idx / H_;
        const int K   = idx - row * H_;
        const float x = (row < P2_) ? W[idx] : 0.0f;
        __nv_bfloat16 hi = __float2bfloat16(x);
        __nv_bfloat16 lo = __float2bfloat16(x - __bfloat162float(hi));
        const int o   = K & 15;
        const int pos = ((o >> 2) * 2) + (o & 1) + ((o >> 1) & 1) * 8;
        const int didx = row * H_ + (K & ~15) + pos;
        g_wsplit[0][didx] = hi;
        g_wsplit[1][didx] = lo;
        return;
    }

    const int b = blockIdx.x - 144;
    if (tid == 0) cue_sh = 0;
    __syncthreads();

    const int id0 = ids[b * 2 + 0], id1 = ids[b * 2 + 1];
    const float* h0 = hs + ((size_t)b * S_ + id0) * H_;
    const float* h1 = hs + ((size_t)b * S_ + id1) * H_;
    #pragma unroll
    for (int h = tid; h < H_; h += 256) s[h] = h0[h] + h1[h];

    int local = 0;
    #pragma unroll
    for (int t = tid; t < S_; t += 256) local += mask[b * S_ + t];
    #pragma unroll
    for (int o = 16; o; o >>= 1) local += __shfl_down_sync(0xffffffffu, local, o);
    if ((tid & 31) == 0) atomicAdd(&cue_sh, local);
    __syncthreads();

    const int warp = tid >> 5, lane = tid & 31;
    for (int p = warp; p < P2_; p += 8) {
        const float* wp = W + (size_t)p * H_;
        float acc = 0.f;
        #pragma unroll
        for (int h = 0; h < H_; h += 32) acc += s[h + lane] * __ldg(wp + h + lane);
        #pragma unroll
        for (int o = 16; o; o >>= 1) acc += __shfl_down_sync(0xffffffffu, acc, o);
        if (lane == 0) g_sdot[b * 48 + p] = acc;
    }
    if (tid == 0) g_cue[b] = cue_sh;
}

// ---------------------------------------------------------------------------
// Warp-MMA helpers (base ISA, compiles on plain sm_103 target)
// ---------------------------------------------------------------------------
__device__ __forceinline__ void ldsm4(uint32_t* r, uint32_t addr) {
    asm volatile("ldmatrix.sync.aligned.m8n8.x4.shared.b16 {%0,%1,%2,%3}, [%4];"
                 : "=r"(r[0]), "=r"(r[1]), "=r"(r[2]), "=r"(r[3]) : "r"(addr));
}
__device__ __forceinline__ void mma_bf16(float* c, const uint32_t* a,
                                         const uint32_t* b) {
    asm volatile(
        "mma.sync.aligned.m16n8k16.row.col.f32.bf16.bf16.f32 "
        "{%0,%1,%2,%3}, {%4,%5,%6,%7}, {%8,%9}, {%0,%1,%2,%3};"
        : "+f"(c[0]), "+f"(c[1]), "+f"(c[2]), "+f"(c[3])
        : "r"(a[0]), "r"(a[1]), "r"(a[2]), "r"(a[3]), "r"(b[0]), "r"(b[1]));
}
__device__ __forceinline__ uint32_t cvt2(float hiE, float loE) {
    uint32_t d;
    asm("cvt.rn.bf16x2.f32 %0, %1, %2;" : "=r"(d) : "f"(hiE), "f"(loE));
    return d;
}
__device__ __forceinline__ void cpa16(uint32_t dst, const void* src) {
    asm volatile("cp.async.ca.shared.global [%0], [%1], 16;"
                 :: "r"(dst), "l"(src));
}

// ---------------------------------------------------------------------------
// Main: K-split split-precision bf16 mma.sync GEMM + fused epilogue.
// 512 CTAs x 256 threads, 4 CTAs/SM (single wave, 32 warps/SM).
// Warp w: k-half h=w>>2 (chunks h*12..+11), row group wr=w&3 (rows wr*16..+15).
// A: LDG.128 direct-to-fragment via the K permutation, issued before the
// B-wait so DRAM latency overlaps. B: per-half cp.async ring (3 bufs), each
// half loads its own B and syncs only itself via named barrier -> halves
// free-run. Final cross-half reduction in smem. D = Ah*Wh + Ah*Wl + Al*Wh.
// ---------------------------------------------------------------------------
__global__ void __launch_bounds__(256, 4) main_kernel(
    const float* __restrict__ hs, const float* __restrict__ bias,
    float* __restrict__ out)
{
    __shared__ __align__(16) char smem[6 * WBUF];    // 46080 B
    const uint32_t sb = (uint32_t)__cvta_generic_to_shared(smem);
    const int tid = threadIdx.x, w = tid >> 5, l = tid & 31;
    const int h  = w >> 2;              // k-half
    const int wr = w & 3;               // row group within CTA
    const int lt = tid & 127;           // thread id within half
    const int r0 = blockIdx.x * MT, b = r0 >> 9;

    // --- B producer (per half): 384 x 16B segs, 3 per thread ---
    auto cpB = [&](int it) {
        const int sl = it % 3;           // ring slot
        #pragma unroll
        for (int i = 0; i < 3; i++) {
            int g  = lt + i * 128;           // 0..383
            int p  = g / 192;                // hi/lo
            int rr = (g % 192) >> 2;         // row 0..47
            int q  = g & 3;                  // 16B granule
            cpa16(sb + (h * 3 + sl) * WBUF + p * WB + rr * 80 + q * 16,
                  &g_wsplit[p][rr * H_ + (h * NIT + it) * CK + q * 8]);
        }
        asm volatile("cp.async.commit_group;");
    };

    // --- A: direct-to-fragment LDG.128 (permuted K) ---
    const int ar  = wr * 16 + (l >> 2);
    const int ac4 = (l & 3) * 4;
    const float* gA = hs + (size_t)(r0 + ar) * H_ + ac4;

    float acc[6][4];
    #pragma unroll
    for (int nt = 0; nt < 6; nt++)
        #pragma unroll
        for (int k = 0; k < 4; k++) acc[nt][k] = 0.f;

    cpB(0); cpB(1);

    // ldmatrix x4 B address: lanes 0-15 -> n-tile nt, lanes 16-31 -> nt+1
    const int il = l & 15;
    const uint32_t bA = (uint32_t)((il & 7) * 80 + (il >> 3) * 16 + (l >> 4) * NT6);
    const int barid = h + 1;             // named barrier per half

    for (int it = 0; it < NIT; it++) {
        // Issue this chunk's A loads first: independent of B arrival, the
        // DRAM latency overlaps the wait_group + barrier below.
        const int kb = (h * NIT + it) * CK;
        float4 aF0 = *(const float4*)(gA + kb);
        float4 aF1 = *(const float4*)(gA + 8 * H_ + kb);
        float4 aF2 = *(const float4*)(gA + kb + 16);
        float4 aF3 = *(const float4*)(gA + 8 * H_ + kb + 16);

        if (it + 1 < NIT)
            asm volatile("cp.async.wait_group 1;" ::: "memory");
        else
            asm volatile("cp.async.wait_group 0;" ::: "memory");
        asm volatile("bar.sync %0, 128;" :: "r"(barid) : "memory");
        if (it + 2 < NIT) cpB(it + 2);

        const uint32_t sbase = sb + (h * 3 + it % 3) * WBUF;
        #pragma unroll
        for (int ks = 0; ks < 2; ks++) {
            // Convert this ks group's A to hi/lo fragments (8 live regs each)
            const float4 vA = (ks == 0) ? aF0 : aF2;   // (r,   cols)
            const float4 vB = (ks == 0) ? aF1 : aF3;   // (r+8, cols)
            uint32_t ah[4], al[4];
            {
                uint32_t hxy = cvt2(vA.y, vA.x);
                uint32_t hzw = cvt2(vA.w, vA.z);
                float e0 = __uint_as_float(hxy << 16);
                float e1 = __uint_as_float(hxy & 0xffff0000u);
                float e2 = __uint_as_float(hzw << 16);
                float e3 = __uint_as_float(hzw & 0xffff0000u);
                ah[0] = hxy; ah[2] = hzw;
                al[0] = cvt2(vA.y - e1, vA.x - e0);
                al[2] = cvt2(vA.w - e3, vA.z - e2);
            }
            {
                uint32_t hxy = cvt2(vB.y, vB.x);
                uint32_t hzw = cvt2(vB.w, vB.z);
                float e0 = __uint_as_float(hxy << 16);
                float e1 = __uint_as_float(hxy & 0xffff0000u);
                float e2 = __uint_as_float(hzw << 16);
                float e3 = __uint_as_float(hzw & 0xffff0000u);
                ah[1] = hxy; ah[3] = hzw;
                al[1] = cvt2(vB.y - e1, vB.x - e0);
                al[3] = cvt2(vB.w - e3, vB.z - e2);
            }
            #pragma unroll
            for (int pp = 0; pp < 3; pp++) {   // n-tile pairs (0,1)(2,3)(4,5)
                uint32_t bh[4], bl[4];
                const uint32_t ba = sbase + pp * 2 * NT6 + bA + ks * 32;
                ldsm4(bh, ba);
                ldsm4(bl, ba + WB);
                mma_bf16(acc[2 * pp],     ah, bh);
                mma_bf16(acc[2 * pp],     ah, bl);
                mma_bf16(acc[2 * pp],     al, bh);
                mma_bf16(acc[2 * pp + 1], ah, bh + 2);
                mma_bf16(acc[2 * pp + 1], ah, bl + 2);
                mma_bf16(acc[2 * pp + 1], al, bh + 2);
            }
        }
    }

    // --- K-split reduction: half-1 dumps partials into smem (B ring dead) ---
    __syncthreads();
    float* rbuf = (float*)smem;              // [64][48] f32 = 12 KB
    const int mrow = wr * 16 + (l >> 2);
    if (h == 1) {
        #pragma unroll
        for (int nt = 0; nt < 6; nt++) {
            const int col = nt * 8 + (l & 3) * 2;
            *(float2*)&rbuf[mrow * 48 + col]       = make_float2(acc[nt][0], acc[nt][1]);
            *(float2*)&rbuf[(mrow + 8) * 48 + col] = make_float2(acc[nt][2], acc[nt][3]);
        }
    }
    __syncthreads();
    if (h == 1) return;

    // --- Epilogue (half-0): x = D + bias + (t<cue)*sdot ; out = sigmoid^4 ---
    const int cue = g_cue[b];
    const int t0  = (r0 & (S_ - 1)) + mrow;
    const float f0 = (t0 < cue) ? 1.0f : 0.0f;
    const float f1 = (t0 + 8 < cue) ? 1.0f : 0.0f;
    float* o0 = out + (size_t)(r0 + mrow) * P2_;
    float* o1 = o0 + 8 * P2_;

    #pragma unroll
    for (int nt = 0; nt < 6; nt++) {
        const int col = nt * 8 + (l & 3) * 2;
        if (col >= P2_) continue;                // drops cols 46,47
        float2 p0 = *(const float2*)&rbuf[mrow * 48 + col];
        float2 p1 = *(const float2*)&rbuf[(mrow + 8) * 48 + col];
        const float b0 = __ldg(bias + col),     b1 = __ldg(bias + col + 1);
        const float s0 = g_sdot[b * 48 + col],  s1 = g_sdot[b * 48 + col + 1];

        float x00 = acc[nt][0] + p0.x + b0 + f0 * s0;
        float x01 = acc[nt][1] + p0.y + b1 + f0 * s1;
        float x10 = acc[nt][2] + p1.x + b0 + f1 * s0;
        float x11 = acc[nt][3] + p1.y + b1 + f1 * s1;
        float g00 = 1.f / (1.f + __expf(-x00)); g00 *= g00; g00 *= g00;
        float g01 = 1.f / (1.f + __expf(-x01)); g01 *= g01; g01 *= g01;
        float g10 = 1.f / (1.f + __expf(-x10)); g10 *= g10; g10 *= g10;
        float g11 = 1.f / (1.f + __expf(-x11)); g11 *= g11; g11 *= g11;
        *(float2*)(o0 + col) = make_float2(g00, g01);
        *(float2*)(o1 + col) = make_float2(g10, g11);
    }
}

// ---------------------------------------------------------------------------
// Launch
// ---------------------------------------------------------------------------
extern "C" void kernel_launch(void* const* d_in, const int* in_sizes, int n_in,
                              void* d_out, int out_size)
{
    const float* hs   = (const float*)d_in[0];  // [64,512,768] f32
    const int*   ids  = (const int*)  d_in[1];  // [64,2] i32
    const int*   mask = (const int*)  d_in[2];  // [64,512] i32
    const float* W    = (const float*)d_in[3];  // [46,768] f32
    const float* bias = (const float*)d_in[4];  // [46] f32
    float*       out  = (float*)d_out;          // [64,512,46] f32

    combo_kernel<<<144 + B_, 256>>>(hs, ids, mask, W);
    main_kernel<<<(B_ * S_) / MT, 256>>>(hs, bias, out);
}

// round 16
// speedup vs baseline: 1.0988x; 1.0069x over previous
#include <cuda_runtime.h>
#include <cuda_bf16.h>
#include <cstdint>

// Problem constants
#define B_   64
#define S_   512
#define H_   768
#define P2_  46
#define MT   64            // M rows per CTA
#define CK   32            // K elems per chunk
#define NIT  12            // chunks per k-half

// B smem: k-major tiles, 32 k-rows x 48 n (96B) padded to 112B pitch
// (112/16=7 -> r*7 mod 8 distinct -> conflict-free ldmatrix.trans).
// Per buffer {hi tile, lo tile}; ring of 3 per k-half (prefetch distance 2).
#define PITCH 112
#define TSZ   (32 * PITCH)     // 3584
#define BUFSZ (2 * TSZ)        // 7168

// Scratch (no cudaMalloc allowed)
__device__ float g_sdot[B_ * 48];
__device__ int   g_cue[B_];
// K-PERMUTED, K-MAJOR split W: element (orig k K, n) stored at row
// kp = (K&~15) + pos(K&15), pos(o) = 2*(o>>2) + (o&1) + 8*((o>>1)&1),
// col n (48 cols, rows dense 96B). A-side float4 fragment loads realize the
// same permutation, so the GEMM sum over K is unchanged. n=46,47 zeroed.
__device__ __nv_bfloat16 g_wsplit2[2][H_ * 48];

// ---------------------------------------------------------------------------
// Combo kernel: blocks [0,24) = W split+transpose (k32 tiles);
// blocks [24,280) = prep, 4 blocks per batch (12 p's each).
// ---------------------------------------------------------------------------
__global__ void __launch_bounds__(256) combo_kernel(
    const float* __restrict__ hs, const int* __restrict__ ids,
    const int* __restrict__ mask, const float* __restrict__ W)
{
    __shared__ float s[H_];
    __shared__ int cue_sh;
    __shared__ __nv_bfloat16 shi[48 * 32], slo[48 * 32];
    const int tid = threadIdx.x;

    if (blockIdx.x < 24) {                       // ---- wconv transpose ----
        const int kbase = blockIdx.x * 32;
        for (int idx = tid; idx < 48 * 32; idx += 256) {
            const int n = idx >> 5, kl = idx & 31;
            const float x = (n < P2_) ? W[n * H_ + kbase + kl] : 0.0f;
            __nv_bfloat16 hi = __float2bfloat16(x);
            __nv_bfloat16 lo = __float2bfloat16(x - __bfloat162float(hi));
            shi[n * 32 + kl] = hi;
            slo[n * 32 + kl] = lo;
        }
        __syncthreads();
        for (int idx = tid; idx < 48 * 32; idx += 256) {
            const int kl = idx / 48, n = idx - kl * 48;
            const int K = kbase + kl, o = K & 15;
            const int kp = (K & ~15) + ((o >> 2) * 2) + (o & 1) + ((o >> 1) & 1) * 8;
            g_wsplit2[0][kp * 48 + n] = shi[n * 32 + kl];
            g_wsplit2[1][kp * 48 + n] = slo[n * 32 + kl];
        }
        return;
    }

    const int pb = blockIdx.x - 24;              // ---- prep ----
    const int b = pb >> 2, pg = pb & 3;
    if (tid == 0) cue_sh = 0;
    __syncthreads();

    const int id0 = ids[b * 2 + 0], id1 = ids[b * 2 + 1];
    const float* h0 = hs + ((size_t)b * S_ + id0) * H_;
    const float* h1 = hs + ((size_t)b * S_ + id1) * H_;
    #pragma unroll
    for (int h = tid; h < H_; h += 256) s[h] = h0[h] + h1[h];

    if (pg == 0) {
        int local = 0;
        #pragma unroll
        for (int t = tid; t < S_; t += 256) local += mask[b * S_ + t];
        #pragma unroll
        for (int o = 16; o; o >>= 1) local += __shfl_down_sync(0xffffffffu, local, o);
        if ((tid & 31) == 0) atomicAdd(&cue_sh, local);
    }
    __syncthreads();

    const int warp = tid >> 5, lane = tid & 31;
    const int pend = pg * 12 + 12;
    for (int p = pg * 12 + warp; p < pend && p < P2_; p += 8) {
        const float* wp = W + (size_t)p * H_;
        float acc = 0.f;
        #pragma unroll
        for (int h = 0; h < H_; h += 32) acc += s[h + lane] * __ldg(wp + h + lane);
        #pragma unroll
        for (int o = 16; o; o >>= 1) acc += __shfl_down_sync(0xffffffffu, acc, o);
        if (lane == 0) g_sdot[b * 48 + p] = acc;
    }
    if (pg == 0 && tid == 0) g_cue[b] = cue_sh;
}

// ---------------------------------------------------------------------------
// Warp-MMA helpers (base ISA, compiles on plain sm_103 target)
// ---------------------------------------------------------------------------
__device__ __forceinline__ void ldsm4t(uint32_t* r, uint32_t addr) {
    asm volatile("ldmatrix.sync.aligned.m8n8.x4.trans.shared.b16 {%0,%1,%2,%3}, [%4];"
                 : "=r"(r[0]), "=r"(r[1]), "=r"(r[2]), "=r"(r[3]) : "r"(addr));
}
__device__ __forceinline__ void mma_bf16(float* c, const uint32_t* a,
                                         const uint32_t* b) {
    asm volatile(
        "mma.sync.aligned.m16n8k16.row.col.f32.bf16.bf16.f32 "
        "{%0,%1,%2,%3}, {%4,%5,%6,%7}, {%8,%9}, {%0,%1,%2,%3};"
        : "+f"(c[0]), "+f"(c[1]), "+f"(c[2]), "+f"(c[3])
        : "r"(a[0]), "r"(a[1]), "r"(a[2]), "r"(a[3]), "r"(b[0]), "r"(b[1]));
}
__device__ __forceinline__ uint32_t cvt2(float hiE, float loE) {
    uint32_t d;
    asm("cvt.rn.bf16x2.f32 %0, %1, %2;" : "=r"(d) : "f"(hiE), "f"(loE));
    return d;
}
__device__ __forceinline__ void cpa16(uint32_t dst, const void* src) {
    asm volatile("cp.async.ca.shared.global [%0], [%1], 16;"
                 :: "r"(dst), "l"(src));
}
__device__ __forceinline__ void pf_l2(const void* p) {
    asm volatile("prefetch.global.L2 [%0];" :: "l"(p));
}

// ---------------------------------------------------------------------------
// Main: K-split split-precision bf16 mma.sync GEMM + fused epilogue.
// 512 CTAs x 256 threads, 4 CTAs/SM (launch_bounds caps regs at 64).
// Warp w: k-half h=w>>2 (chunks h*12..+11), row group wr=w&3 (rows wr*16..+15).
// A: LDG.128 streaming direct-to-fragment (K-permuted), next chunk L2-
// prefetched. B: k-major smem ring (3 bufs/half), ldmatrix.x4.trans, cp.async
// fully dense in gmem. Halves sync only themselves via named barriers.
// Epilogue split by n-tiles across halves. D = Ah*Wh + Ah*Wl + Al*Wh.
// ---------------------------------------------------------------------------
__global__ void __launch_bounds__(256, 4) main_kernel(
    const float* __restrict__ hs, const float* __restrict__ bias,
    float* __restrict__ out)
{
    __shared__ __align__(16) char smem[6 * BUFSZ];   // 43008 B
    const uint32_t sb = (uint32_t)__cvta_generic_to_shared(smem);
    const int tid = threadIdx.x, w = tid >> 5, l = tid & 31;
    const int h  = w >> 2;              // k-half
    const int wr = w & 3;               // row group within CTA
    const int lt = tid & 127;           // thread id within half
    const int r0 = blockIdx.x * MT, b = r0 >> 9;

    // --- B producer (per half): 384 dense 16B segs, 3 per thread ---
    auto cpB = [&](int it) {
        const int sl = it % 3;
        const uint32_t dbase = sb + (h * 3 + sl) * BUFSZ;
        const int krow0 = (h * NIT + it) * CK;       // global (permuted) k row
        #pragma unroll
        for (int i = 0; i < 3; i++) {
            int g  = lt + i * 128;           // 0..383
            int p  = g / 192;                // hi/lo level
            int r  = g - p * 192;
            int kr = r / 6;                  // k row 0..31
            int q  = r - kr * 6;             // 16B granule 0..5
            cpa16(dbase + p * TSZ + kr * PITCH + q * 16,
                  (const char*)&g_wsplit2[p][0] + (size_t)(krow0 + kr) * 96 + q * 16);
        }
        asm volatile("cp.async.commit_group;");
    };

    // --- A: direct-to-fragment LDG.128 (permuted K), streaming ---
    const int ar  = wr * 16 + (l >> 2);
    const int ac4 = (l & 3) * 4;
    const float* gA = hs + (size_t)(r0 + ar) * H_ + ac4;

    float acc[6][4];
    #pragma unroll
    for (int nt = 0; nt < 6; nt++)
        #pragma unroll
        for (int k = 0; k < 4; k++) acc[nt][k] = 0.f;

    cpB(0); cpB(1);

    // ldmatrix.trans B address: lane -> k-row (l&7)+((l>>3)&1)*8, n-16B (l>>4)
    const uint32_t bA = (uint32_t)(((l & 7) + ((l >> 3) & 1) * 8) * PITCH
                                   + (l >> 4) * 16);
    const int barid = h + 1;             // named barrier per half

    for (int it = 0; it < NIT; it++) {
        const int kb = (h * NIT + it) * CK;
        float4 aF0 = __ldcs((const float4*)(gA + kb));
        float4 aF1 = __ldcs((const float4*)(gA + 8 * H_ + kb));
        float4 aF2 = __ldcs((const float4*)(gA + kb + 16));
        float4 aF3 = __ldcs((const float4*)(gA + 8 * H_ + kb + 16));
        if (it + 1 < NIT) {              // L2-prefetch next chunk's A
            const int kn = kb + CK;
            pf_l2(gA + kn);
            pf_l2(gA + 8 * H_ + kn);
            pf_l2(gA + kn + 16);
            pf_l2(gA + 8 * H_ + kn + 16);
        }

        if (it + 1 < NIT)
            asm volatile("cp.async.wait_group 1;" ::: "memory");
        else
            asm volatile("cp.async.wait_group 0;" ::: "memory");
        asm volatile("bar.sync %0, 128;" :: "r"(barid) : "memory");
        if (it + 2 < NIT) cpB(it + 2);   // slot (it+2)%3 != reading slot it%3

        const uint32_t sbase = sb + (h * 3 + it % 3) * BUFSZ;
        #pragma unroll
        for (int ks = 0; ks < 2; ks++) {
            const float4 vA = (ks == 0) ? aF0 : aF2;   // (row r)
            const float4 vB = (ks == 0) ? aF1 : aF3;   // (row r+8)
            uint32_t ah[4], al[4];
            {
                uint32_t hxy = cvt2(vA.y, vA.x);
                uint32_t hzw = cvt2(vA.w, vA.z);
                float e0 = __uint_as_float(hxy << 16);
                float e1 = __uint_as_float(hxy & 0xffff0000u);
                float e2 = __uint_as_float(hzw << 16);
                float e3 = __uint_as_float(hzw & 0xffff0000u);
                ah[0] = hxy; ah[2] = hzw;
                al[0] = cvt2(vA.y - e1, vA.x - e0);
                al[2] = cvt2(vA.w - e3, vA.z - e2);
            }
            {
                uint32_t hxy = cvt2(vB.y, vB.x);
                uint32_t hzw = cvt2(vB.w, vB.z);
                float e0 = __uint_as_float(hxy << 16);
                float e1 = __uint_as_float(hxy & 0xffff0000u);
                float e2 = __uint_as_float(hzw << 16);
                float e3 = __uint_as_float(hzw & 0xffff0000u);
                ah[1] = hxy; ah[3] = hzw;
                al[1] = cvt2(vB.y - e1, vB.x - e0);
                al[3] = cvt2(vB.w - e3, vB.z - e2);
            }
            #pragma unroll
            for (int pp = 0; pp < 3; pp++) {   // n-tile pairs (0,1)(2,3)(4,5)
                uint32_t bh[4], bl[4];
                const uint32_t ba = sbase + ks * (16 * PITCH) + pp * 32 + bA;
                ldsm4t(bh, ba);
                ldsm4t(bl, ba + TSZ);
                mma_bf16(acc[2 * pp],     ah, bh);
                mma_bf16(acc[2 * pp],     ah, bl);
                mma_bf16(acc[2 * pp],     al, bh);
                mma_bf16(acc[2 * pp + 1], ah, bh + 2);
                mma_bf16(acc[2 * pp + 1], ah, bl + 2);
                mma_bf16(acc[2 * pp + 1], al, bh + 2);
            }
        }
    }

    // --- Cross-half exchange: each half shares 3 n-tiles (ring dead) ---
    __syncthreads();
    float* rA = (float*)smem;                 // [64][24]: half-0's nt 3..5
    float* rB = (float*)(smem + 6144);        // [64][24]: half-1's nt 0..2
    const int mrow = wr * 16 + (l >> 2);
    const int colq = (l & 3) * 2;
    if (h == 0) {
        #pragma unroll
        for (int nt = 3; nt < 6; nt++) {
            const int c24 = (nt - 3) * 8 + colq;
            *(float2*)&rA[mrow * 24 + c24]       = make_float2(acc[nt][0], acc[nt][1]);
            *(float2*)&rA[(mrow + 8) * 24 + c24] = make_float2(acc[nt][2], acc[nt][3]);
        }
    } else {
        #pragma unroll
        for (int nt = 0; nt < 3; nt++) {
            const int c24 = nt * 8 + colq;
            *(float2*)&rB[mrow * 24 + c24]       = make_float2(acc[nt][0], acc[nt][1]);
            *(float2*)&rB[(mrow + 8) * 24 + c24] = make_float2(acc[nt][2], acc[nt][3]);
        }
    }
    __syncthreads();

    // --- Epilogue: x = D + bias + (t<cue)*sdot ; out = sigmoid(x)^4 ---
    const int cue = g_cue[b];
    const int t0  = (r0 & (S_ - 1)) + mrow;
    const float f0 = (t0 < cue) ? 1.0f : 0.0f;
    const float f1 = (t0 + 8 < cue) ? 1.0f : 0.0f;
    float* o0 = out + (size_t)(r0 + mrow) * P2_;
    float* o1 = o0 + 8 * P2_;

    const int ntlo = (h == 0) ? 0 : 3;        // half-0 stores nt 0-2, half-1 3-5
    #pragma unroll
    for (int ntq = 0; ntq < 3; ntq++) {
        const int nt  = ntlo + ntq;
        const int col = nt * 8 + colq;
        if (col >= P2_) continue;             // drops cols 46,47 (h==1 only)
        const int c24 = (h == 0) ? col : (col - 24);
        const float* rp = (h == 0) ? rB : rA;
        float2 p0 = *(const float2*)&rp[mrow * 24 + c24];
        float2 p1 = *(const float2*)&rp[(mrow + 8) * 24 + c24];
        const float b0 = __ldg(bias + col),     b1 = __ldg(bias + col + 1);
        const float s0 = g_sdot[b * 48 + col],  s1 = g_sdot[b * 48 + col + 1];

        float x00 = acc[nt][0] + p0.x + b0 + f0 * s0;
        float x01 = acc[nt][1] + p0.y + b1 + f0 * s1;
        float x10 = acc[nt][2] + p1.x + b0 + f1 * s0;
        float x11 = acc[nt][3] + p1.y + b1 + f1 * s1;
        float g00 = 1.f / (1.f + __expf(-x00)); g00 *= g00; g00 *= g00;
        float g01 = 1.f / (1.f + __expf(-x01)); g01 *= g01; g01 *= g01;
        float g10 = 1.f / (1.f + __expf(-x10)); g10 *= g10; g10 *= g10;
        float g11 = 1.f / (1.f + __expf(-x11)); g11 *= g11; g11 *= g11;
        *(float2*)(o0 + col) = make_float2(g00, g01);
        *(float2*)(o1 + col) = make_float2(g10, g11);
    }
}

// ---------------------------------------------------------------------------
// Launch
// ---------------------------------------------------------------------------
extern "C" void kernel_launch(void* const* d_in, const int* in_sizes, int n_in,
                              void* d_out, int out_size)
{
    const float* hs   = (const float*)d_in[0];  // [64,512,768] f32
    const int*   ids  = (const int*)  d_in[1];  // [64,2] i32
    const int*   mask = (const int*)  d_in[2];  // [64,512] i32
    const float* W    = (const float*)d_in[3];  // [46,768] f32
    const float* bias = (const float*)d_in[4];  // [46] f32
    float*       out  = (float*)d_out;          // [64,512,46] f32

    combo_kernel<<<24 + 4 * B_, 256>>>(hs, ids, mask, W);
    main_kernel<<<(B_ * S_) / MT, 256>>>(hs, bias, out);
}

// round 17
// speedup vs baseline: 1.1560x; 1.0520x over previous
#include <cuda_runtime.h>
#include <cuda_bf16.h>
#include <cstdint>

// Problem constants
#define B_   64
#define S_   512
#define H_   768
#define P2_  46
#define MT   128           // M rows per CTA (2 m16 tiles per warp)
#define CK   32            // K elems per chunk
#define NIT  12            // chunks per k-half

// B smem (R14 layout): n-major rows, 80B pitch (64B data = 32 k bf16).
// Per buffer {W_hi 48x80B, W_lo 48x80B}; ring of 3 per k-half (6 total).
// Ring depth 3 REQUIRED at prefetch distance 2 (depth 2 races: R9 failure).
#define WB    3840         // 48*80: lo-level offset within buffer
#define WBUF  7680
#define NT6   640          // 8 rows * 80B per n-tile

// Scratch (no cudaMalloc allowed)
__device__ float g_sdot[B_ * 48];
__device__ int   g_cue[B_];
// K-PERMUTED split W, n-major: within each 16-col group, orig col o stored at
// pos = 2*(o>>2) + (o&1) + 8*((o>>1)&1). A-side float4 fragment loads realize
// the same map, so the GEMM sum over K is unchanged. Rows 46-47 zeroed.
__device__ __nv_bfloat16 g_wsplit[2][48 * H_];

// ---------------------------------------------------------------------------
// Combo kernel: blocks [0,144) = permuted W split (n-major, coalesced);
// blocks [144,400) = prep, 4 blocks per batch (12 p's each).
// ---------------------------------------------------------------------------
__global__ void __launch_bounds__(256) combo_kernel(
    const float* __restrict__ hs, const int* __restrict__ ids,
    const int* __restrict__ mask, const float* __restrict__ W)
{
    __shared__ float s[H_];
    __shared__ int cue_sh;
    const int tid = threadIdx.x;

    if (blockIdx.x < 144) {                      // ---- wconv (n-major) ----
        const int idx = blockIdx.x * 256 + tid;  // < 48*768 exactly
        const int row = idx / H_;
        const int K   = idx - row * H_;
        const float x = (row < P2_) ? W[idx] : 0.0f;
        __nv_bfloat16 hi = __float2bfloat16(x);
        __nv_bfloat16 lo = __float2bfloat16(x - __bfloat162float(hi));
        const int o   = K & 15;
        const int pos = ((o >> 2) * 2) + (o & 1) + ((o >> 1) & 1) * 8;
        const int didx = row * H_ + (K & ~15) + pos;
        g_wsplit[0][didx] = hi;
        g_wsplit[1][didx] = lo;
        return;
    }

    const int pb = blockIdx.x - 144;             // ---- prep (4x split) ----
    const int b = pb >> 2, pg = pb & 3;
    if (tid == 0) cue_sh = 0;
    __syncthreads();

    const int id0 = ids[b * 2 + 0], id1 = ids[b * 2 + 1];
    const float* h0 = hs + ((size_t)b * S_ + id0) * H_;
    const float* h1 = hs + ((size_t)b * S_ + id1) * H_;
    #pragma unroll
    for (int h = tid; h < H_; h += 256) s[h] = h0[h] + h1[h];

    if (pg == 0) {
        int local = 0;
        #pragma unroll
        for (int t = tid; t < S_; t += 256) local += mask[b * S_ + t];
        #pragma unroll
        for (int o = 16; o; o >>= 1) local += __shfl_down_sync(0xffffffffu, local, o);
        if ((tid & 31) == 0) atomicAdd(&cue_sh, local);
    }
    __syncthreads();

    const int warp = tid >> 5, lane = tid & 31;
    const int pend = pg * 12 + 12;
    for (int p = pg * 12 + warp; p < pend && p < P2_; p += 8) {
        const float* wp = W + (size_t)p * H_;
        float acc = 0.f;
        #pragma unroll
        for (int h = 0; h < H_; h += 32) acc += s[h + lane] * __ldg(wp + h + lane);
        #pragma unroll
        for (int o = 16; o; o >>= 1) acc += __shfl_down_sync(0xffffffffu, acc, o);
        if (lane == 0) g_sdot[b * 48 + p] = acc;
    }
    if (pg == 0 && tid == 0) g_cue[b] = cue_sh;
}

// ---------------------------------------------------------------------------
// Warp-MMA helpers (base ISA, compiles on plain sm_103 target)
// ---------------------------------------------------------------------------
__device__ __forceinline__ void ldsm4(uint32_t* r, uint32_t addr) {
    asm volatile("ldmatrix.sync.aligned.m8n8.x4.shared.b16 {%0,%1,%2,%3}, [%4];"
                 : "=r"(r[0]), "=r"(r[1]), "=r"(r[2]), "=r"(r[3]) : "r"(addr));
}
__device__ __forceinline__ void mma_bf16(float* c, const uint32_t* a,
                                         const uint32_t* b) {
    asm volatile(
        "mma.sync.aligned.m16n8k16.row.col.f32.bf16.bf16.f32 "
        "{%0,%1,%2,%3}, {%4,%5,%6,%7}, {%8,%9}, {%0,%1,%2,%3};"
        : "+f"(c[0]), "+f"(c[1]), "+f"(c[2]), "+f"(c[3])
        : "r"(a[0]), "r"(a[1]), "r"(a[2]), "r"(a[3]), "r"(b[0]), "r"(b[1]));
}
__device__ __forceinline__ uint32_t cvt2(float hiE, float loE) {
    uint32_t d;
    asm("cvt.rn.bf16x2.f32 %0, %1, %2;" : "=r"(d) : "f"(hiE), "f"(loE));
    return d;
}
__device__ __forceinline__ void cpa16(uint32_t dst, const void* src) {
    asm volatile("cp.async.ca.shared.global [%0], [%1], 16;"
                 :: "r"(dst), "l"(src));
}

// ---------------------------------------------------------------------------
// Main: K-split split-precision bf16 mma.sync GEMM + fused epilogue.
// 256 CTAs x 256 threads, 2 CTAs/SM (single wave). Warp w: k-half h=w>>2
// (chunks h*12..+11), row group wr=w&3 covering TWO m16 tiles (rows
// wr*32..+31) -> each B fragment pair feeds 12 MMAs (halves B-ldsm traffic).
// A: LDG.128 direct-to-fragment via the K permutation, issued before the
// B-wait. B: per-half cp.async ring (3 bufs), named-barrier sync per half.
// Final cross-half reduction in smem. D = Ah*Wh + Ah*Wl + Al*Wh.
// ---------------------------------------------------------------------------
__global__ void __launch_bounds__(256, 2) main_kernel(
    const float* __restrict__ hs, const float* __restrict__ bias,
    float* __restrict__ out)
{
    __shared__ __align__(16) char smem[6 * WBUF];    // 46080 B
    const uint32_t sb = (uint32_t)__cvta_generic_to_shared(smem);
    const int tid = threadIdx.x, w = tid >> 5, l = tid & 31;
    const int h  = w >> 2;              // k-half
    const int wr = w & 3;               // row group (32 rows)
    const int lt = tid & 127;           // thread id within half
    const int r0 = blockIdx.x * MT, b = r0 >> 9;

    // --- B producer (per half): 384 x 16B segs, 3 per thread ---
    auto cpB = [&](int it) {
        const int sl = it % 3;
        #pragma unroll
        for (int i = 0; i < 3; i++) {
            int g  = lt + i * 128;           // 0..383
            int p  = g / 192;                // hi/lo level
            int rr = (g % 192) >> 2;         // n row 0..47
            int q  = g & 3;                  // 16B granule
            cpa16(sb + (h * 3 + sl) * WBUF + p * WB + rr * 80 + q * 16,
                  &g_wsplit[p][rr * H_ + (h * NIT + it) * CK + q * 8]);
        }
        asm volatile("cp.async.commit_group;");
    };

    // --- A: direct-to-fragment LDG.128 (permuted K) ---
    const int row0 = wr * 32 + (l >> 2);         // tile-0 fragment row
    const int ac4  = (l & 3) * 4;
    const float* gA = hs + (size_t)(r0 + row0) * H_ + ac4;

    float acc[12][4];                            // [t*6 + nt][k]
    #pragma unroll
    for (int i = 0; i < 12; i++)
        #pragma unroll
        for (int k = 0; k < 4; k++) acc[i][k] = 0.f;

    cpB(0); cpB(1);

    // ldsm x4 B address: lanes 0-15 -> n-tile nt, lanes 16-31 -> nt+1
    const int il = l & 15;
    const uint32_t bA = (uint32_t)((il & 7) * 80 + (il >> 3) * 16 + (l >> 4) * NT6);
    const int barid = h + 1;             // named barrier per half

    for (int it = 0; it < NIT; it++) {
        // A loads first: DRAM latency overlaps wait_group + barrier.
        const int kb = (h * NIT + it) * CK;
        float4 aF[8];                    // [t*4 + s*2 + rr]
        #pragma unroll
        for (int t = 0; t < 2; t++)
            #pragma unroll
            for (int s = 0; s < 2; s++)
                #pragma unroll
                for (int rr = 0; rr < 2; rr++)
                    aF[t * 4 + s * 2 + rr] =
                        *(const float4*)(gA + (size_t)(t * 16 + rr * 8) * H_
                                         + kb + s * 16);

        if (it + 1 < NIT)
            asm volatile("cp.async.wait_group 1;" ::: "memory");
        else
            asm volatile("cp.async.wait_group 0;" ::: "memory");
        asm volatile("bar.sync %0, 128;" :: "r"(barid) : "memory");
        if (it + 2 < NIT) cpB(it + 2);   // slot (it+2)%3 != reading slot it%3

        // Convert all A to hi/lo fragments: frag base = t*8 + s*4 + rr,
        // xy pair -> base, zw pair -> base+2.
        uint32_t ahi[16], alo[16];
        #pragma unroll
        for (int idx = 0; idx < 8; idx++) {
            const float4 v = aF[idx];
            const int base = (idx >> 2) * 8 + ((idx >> 1) & 1) * 4 + (idx & 1);
            uint32_t hxy = cvt2(v.y, v.x);
            uint32_t hzw = cvt2(v.w, v.z);
            float e0 = __uint_as_float(hxy << 16);
            float e1 = __uint_as_float(hxy & 0xffff0000u);
            float e2 = __uint_as_float(hzw << 16);
            float e3 = __uint_as_float(hzw & 0xffff0000u);
            ahi[base]     = hxy;
            ahi[base + 2] = hzw;
            alo[base]     = cvt2(v.y - e1, v.x - e0);
            alo[base + 2] = cvt2(v.w - e3, v.z - e2);
        }

        const uint32_t sbase = sb + (h * 3 + it % 3) * WBUF;
        #pragma unroll
        for (int s = 0; s < 2; s++) {
            #pragma unroll
            for (int pp = 0; pp < 3; pp++) {   // n-tile pairs (0,1)(2,3)(4,5)
                uint32_t bh[4], bl[4];
                const uint32_t ba = sbase + pp * 2 * NT6 + bA + s * 32;
                ldsm4(bh, ba);
                ldsm4(bl, ba + WB);
                #pragma unroll
                for (int t = 0; t < 2; t++) {  // both m16 tiles share B frags
                    const uint32_t* ah = ahi + t * 8 + s * 4;
                    const uint32_t* al = alo + t * 8 + s * 4;
                    mma_bf16(acc[t * 6 + 2 * pp],     ah, bh);
                    mma_bf16(acc[t * 6 + 2 * pp],     ah, bl);
                    mma_bf16(acc[t * 6 + 2 * pp],     al, bh);
                    mma_bf16(acc[t * 6 + 2 * pp + 1], ah, bh + 2);
                    mma_bf16(acc[t * 6 + 2 * pp + 1], ah, bl + 2);
                    mma_bf16(acc[t * 6 + 2 * pp + 1], al, bh + 2);
                }
            }
        }
    }

    // --- K-split reduction: half-1 dumps partials into smem (ring dead) ---
    __syncthreads();
    float* rbuf = (float*)smem;              // [128][48] f32 = 24576 B
    if (h == 1) {
        #pragma unroll
        for (int t = 0; t < 2; t++) {
            const int mrow = wr * 32 + t * 16 + (l >> 2);
            #pragma unroll
            for (int nt = 0; nt < 6; nt++) {
                const int col = nt * 8 + (l & 3) * 2;
                *(float2*)&rbuf[mrow * 48 + col] =
                    make_float2(acc[t * 6 + nt][0], acc[t * 6 + nt][1]);
                *(float2*)&rbuf[(mrow + 8) * 48 + col] =
                    make_float2(acc[t * 6 + nt][2], acc[t * 6 + nt][3]);
            }
        }
    }
    __syncthreads();
    if (h == 1) return;

    // --- Epilogue (half-0): x = D + bias + (t<cue)*sdot ; out = sigmoid^4 ---
    const int cue = g_cue[b];
    #pragma unroll
    for (int t = 0; t < 2; t++) {
        const int mrow = wr * 32 + t * 16 + (l >> 2);
        const int t0   = (r0 & (S_ - 1)) + mrow;
        const float f0 = (t0 < cue) ? 1.0f : 0.0f;
        const float f1 = (t0 + 8 < cue) ? 1.0f : 0.0f;
        float* o0 = out + (size_t)(r0 + mrow) * P2_;
        float* o1 = o0 + 8 * P2_;

        #pragma unroll
        for (int nt = 0; nt < 6; nt++) {
            const int col = nt * 8 + (l & 3) * 2;
            if (col >= P2_) continue;            // drops cols 46,47
            float2 p0 = *(const float2*)&rbuf[mrow * 48 + col];
            float2 p1 = *(const float2*)&rbuf[(mrow + 8) * 48 + col];
            const float b0 = __ldg(bias + col),     b1 = __ldg(bias + col + 1);
            const float s0 = g_sdot[b * 48 + col],  s1 = g_sdot[b * 48 + col + 1];

            float x00 = acc[t * 6 + nt][0] + p0.x + b0 + f0 * s0;
            float x01 = acc[t * 6 + nt][1] + p0.y + b1 + f0 * s1;
            float x10 = acc[t * 6 + nt][2] + p1.x + b0 + f1 * s0;
            float x11 = acc[t * 6 + nt][3] + p1.y + b1 + f1 * s1;
            float g00 = 1.f / (1.f + __expf(-x00)); g00 *= g00; g00 *= g00;
            float g01 = 1.f / (1.f + __expf(-x01)); g01 *= g01; g01 *= g01;
            float g10 = 1.f / (1.f + __expf(-x10)); g10 *= g10; g10 *= g10;
            float g11 = 1.f / (1.f + __expf(-x11)); g11 *= g11; g11 *= g11;
            *(float2*)(o0 + col) = make_float2(g00, g01);
            *(float2*)(o1 + col) = make_float2(g10, g11);
        }
    }
}

// ---------------------------------------------------------------------------
// Launch
// ---------------------------------------------------------------------------
extern "C" void kernel_launch(void* const* d_in, const int* in_sizes, int n_in,
                              void* d_out, int out_size)
{
    const float* hs   = (const float*)d_in[0];  // [64,512,768] f32
    const int*   ids  = (const int*)  d_in[1];  // [64,2] i32
    const int*   mask = (const int*)  d_in[2];  // [64,512] i32
    const float* W    = (const float*)d_in[3];  // [46,768] f32
    const float* bias = (const float*)d_in[4];  // [46] f32
    float*       out  = (float*)d_out;          // [64,512,46] f32

    combo_kernel<<<144 + 4 * B_, 256>>>(hs, ids, mask, W);
    main_kernel<<<(B_ * S_) / MT, 256>>>(hs, bias, out);
}